// round 4
// baseline (speedup 1.0000x reference)
#include <cuda_runtime.h>
#include <cstdint>

// PRALoss fused single-kernel reduction.
// Inputs: D_est [32,1,1024,1024] fp32, D_gt same. Output: scalar fp32.
//
// Per pixel (h,w):
//   s_est = sum_b est, s_gt = sum_b gt  -> mask = (s_est > s_gt)
//   sq_est = sum_b est^2, sq_diff = sum_b (est-gt)^2
// Global: diff2 = sum sq_diff ; G2 = sum sq_est ; H2 = sum sq_est*mask
// out = diff2/G2 + 0.1 * diff2/H2
//
// 1024 blocks x 256 threads, single wave. Each block writes 3 fp32
// partials to __device__ scratch, then the LAST block to finish
// (atomic counter) reduces all partials in fp64 (fixed order,
// deterministic) and writes the scalar. Counter self-resets so the
// kernel is graph-replayable. No second launch.

#define BATCH 32
#define PLANE_F4 (1024 * 1024 / 4)   // float4 elements per [H,W] plane
#define THREADS 256
#define NBLOCKS (PLANE_F4 / THREADS) // 1024

__device__ float g_part[3][NBLOCKS]; // [0]=diff2, [1]=G2, [2]=H2 per block
__device__ unsigned int g_count = 0;

__global__ __launch_bounds__(THREADS) void pra_fused(const float4* __restrict__ est,
                                                     const float4* __restrict__ gt,
                                                     float* __restrict__ out) {
    const int idx = blockIdx.x * THREADS + threadIdx.x;   // one float4-pixel group

    float4 s_est = make_float4(0.f, 0.f, 0.f, 0.f);
    float4 s_gt  = make_float4(0.f, 0.f, 0.f, 0.f);
    float4 sqe   = make_float4(0.f, 0.f, 0.f, 0.f);
    float4 sqd   = make_float4(0.f, 0.f, 0.f, 0.f);

#pragma unroll 4
    for (int b = 0; b < BATCH; b++) {
        const float4 e = est[idx + (size_t)b * PLANE_F4];
        const float4 g = gt [idx + (size_t)b * PLANE_F4];
        s_est.x += e.x; s_est.y += e.y; s_est.z += e.z; s_est.w += e.w;
        s_gt.x  += g.x; s_gt.y  += g.y; s_gt.z  += g.z; s_gt.w  += g.w;
        sqe.x = fmaf(e.x, e.x, sqe.x);
        sqe.y = fmaf(e.y, e.y, sqe.y);
        sqe.z = fmaf(e.z, e.z, sqe.z);
        sqe.w = fmaf(e.w, e.w, sqe.w);
        float dx = e.x - g.x, dy = e.y - g.y, dz = e.z - g.z, dw = e.w - g.w;
        sqd.x = fmaf(dx, dx, sqd.x);
        sqd.y = fmaf(dy, dy, sqd.y);
        sqd.z = fmaf(dz, dz, sqd.z);
        sqd.w = fmaf(dw, dw, sqd.w);
    }

    // per-thread scalars; mask applied per pixel from batch sums
    float d2 = (sqd.x + sqd.y) + (sqd.z + sqd.w);
    float g2 = (sqe.x + sqe.y) + (sqe.z + sqe.w);
    float h2 = (s_est.x > s_gt.x ? sqe.x : 0.f)
             + (s_est.y > s_gt.y ? sqe.y : 0.f)
             + (s_est.z > s_gt.z ? sqe.z : 0.f)
             + (s_est.w > s_gt.w ? sqe.w : 0.f);

    // warp reduce
#pragma unroll
    for (int off = 16; off > 0; off >>= 1) {
        d2 += __shfl_down_sync(0xFFFFFFFFu, d2, off);
        g2 += __shfl_down_sync(0xFFFFFFFFu, g2, off);
        h2 += __shfl_down_sync(0xFFFFFFFFu, h2, off);
    }

    __shared__ float s_d2[THREADS / 32], s_g2[THREADS / 32], s_h2[THREADS / 32];
    const int lane = threadIdx.x & 31;
    const int wid  = threadIdx.x >> 5;
    if (lane == 0) { s_d2[wid] = d2; s_g2[wid] = g2; s_h2[wid] = h2; }
    __syncthreads();

    if (wid == 0) {
        d2 = (lane < THREADS / 32) ? s_d2[lane] : 0.f;
        g2 = (lane < THREADS / 32) ? s_g2[lane] : 0.f;
        h2 = (lane < THREADS / 32) ? s_h2[lane] : 0.f;
#pragma unroll
        for (int off = 4; off > 0; off >>= 1) {
            d2 += __shfl_down_sync(0xFFFFFFFFu, d2, off);
            g2 += __shfl_down_sync(0xFFFFFFFFu, g2, off);
            h2 += __shfl_down_sync(0xFFFFFFFFu, h2, off);
        }
        if (lane == 0) {
            g_part[0][blockIdx.x] = d2;
            g_part[1][blockIdx.x] = g2;
            g_part[2][blockIdx.x] = h2;
        }
    }

    // ---- last-block-done epilogue ----
    __shared__ bool s_is_last;
    if (threadIdx.x == 0) {
        __threadfence();                                  // publish partials
        unsigned int prev = atomicAdd(&g_count, 1u);
        s_is_last = (prev == NBLOCKS - 1);
    }
    __syncthreads();
    if (!s_is_last) return;

    __threadfence();                                      // acquire all partials

    const int t = threadIdx.x;
    double fd2 = 0.0, fg2 = 0.0, fh2 = 0.0;
#pragma unroll
    for (int i = t; i < NBLOCKS; i += THREADS) {
        fd2 += (double)g_part[0][i];
        fg2 += (double)g_part[1][i];
        fh2 += (double)g_part[2][i];
    }

#pragma unroll
    for (int off = 16; off > 0; off >>= 1) {
        fd2 += __shfl_down_sync(0xFFFFFFFFu, fd2, off);
        fg2 += __shfl_down_sync(0xFFFFFFFFu, fg2, off);
        fh2 += __shfl_down_sync(0xFFFFFFFFu, fh2, off);
    }

    __shared__ double f_d2[THREADS / 32], f_g2[THREADS / 32], f_h2[THREADS / 32];
    if (lane == 0) { f_d2[wid] = fd2; f_g2[wid] = fg2; f_h2[wid] = fh2; }
    __syncthreads();

    if (t == 0) {
        double D2 = f_d2[0], G2 = f_g2[0], H2 = f_h2[0];
#pragma unroll
        for (int w = 1; w < THREADS / 32; w++) {
            D2 += f_d2[w]; G2 += f_g2[w]; H2 += f_h2[w];
        }
        g_count = 0;                                      // reset for next replay
        out[0] = (float)(D2 / G2 + 0.1 * (D2 / H2));
    }
}

extern "C" void kernel_launch(void* const* d_in, const int* in_sizes, int n_in,
                              void* d_out, int out_size) {
    const float4* est = (const float4*)d_in[0];
    const float4* gt  = (const float4*)d_in[1];
    float* out = (float*)d_out;

    pra_fused<<<NBLOCKS, THREADS>>>(est, gt, out);
}